// round 10
// baseline (speedup 1.0000x reference)
#include <cuda_runtime.h>
#include <math.h>

// Problem constants: B=8, H=1024, E=512, V=32000, T=100
#define VOCAB 32000
#define BATCH 8
#define HDIM  1024
#define EDIM  512
#define XV    (HDIM + EDIM)        // 1536
#define XK    (2 * HDIM + EDIM)    // 2560
#define TMAX  128

#define NW      4                  // words per tile
#define TILES   (VOCAB / NW)       // 8000
#define DEPTH   3                  // cp.async ring stages per warp
#define STAGEF  (NW * 64)          // floats per stage = 1KB
#define NSTAGES (XV / 64)          // 24 column-chunks
#define CTAS    444                // 148 SMs x 3 CTAs
#define WARPS_PER_CTA 8
#define NWARPS_TOTAL (CTAS * WARPS_PER_CTA)      // 3552
#define STATIC_TILES (2 * NWARPS_TOTAL)          // 7104 static; 896 tail
#define NORM_SLICES 16
#define NORM_GRID (BATCH * NORM_SLICES)

// dynamic smem: xs[8][1536] | rings[8 warps][DEPTH][STAGEF] | rs[8]
#define SMEM_FLOATS (BATCH * XV + WARPS_PER_CTA * DEPTH * STAGEF + 8)
#define SMEM_BYTES  (SMEM_FLOATS * 4)

typedef unsigned long long u64;

__device__ __forceinline__ u64 fma2(u64 a, u64 b, u64 c) {
    u64 d;
    asm("fma.rn.f32x2 %0, %1, %2, %3;" : "=l"(d) : "l"(a), "l"(b), "l"(c));
    return d;
}
__device__ __forceinline__ float f2_lo(u64 a) { return __uint_as_float((unsigned)a); }
__device__ __forceinline__ float f2_hi(u64 a) { return __uint_as_float((unsigned)(a >> 32)); }

__device__ __forceinline__ float exp_tanh(float e) {
    float ec = fminf(fmaxf(e, -9.0f), 9.0f);
    float t  = __expf(2.0f * ec);
    float th = (t - 1.0f) / (t + 1.0f);
    return __expf(th);
}

__device__ __forceinline__ void cp16s(unsigned saddr, const float* gmem_src) {
    asm volatile("cp.async.cg.shared.global [%0], [%1], 16;\n"
                 :: "r"(saddr), "l"(gmem_src) : "memory");
}
#define CP_COMMIT() asm volatile("cp.async.commit_group;\n" ::: "memory")
#define CP_WAIT(N)  asm volatile("cp.async.wait_group %0;\n" :: "n"(N) : "memory")

// device state (counters reset by norm kernel each launch -> replay safe)
__device__ int   g_tile = 0;                 // e_v tail counter
__device__ int   g_fixt = 0;                 // fixup task counter
__device__ float g_rowsum[BATCH] = {};
__device__ int   g_norm_done = 0;
__device__ float g_fix[BATCH * TMAX];        // fixup results (0 = invalid);
                                             // rewritten fully every launch

// 16-value compacting butterfly across a half-warp. Lane l16 ends with index l16.
__device__ __forceinline__ float reduce16(float* v, int l16) {
#pragma unroll
    for (int d = 8; d > 0; d >>= 1) {
#pragma unroll
        for (int i = 0; i < 16; i++) {
            if (i < d) {
                float give = (l16 & d) ? v[i] : v[i + d];
                float got  = __shfl_xor_sync(0xffffffffu, give, d);
                float keep = (l16 & d) ? v[i + d] : v[i];
                v[i] = keep + got;
            }
        }
    }
    return v[0];
}

// ---------------------------------------------------------------------------
// Kernel 1: e_v for ALL words + W_K fixup compute folded in as tail tasks.
// 3 CTAs/SM. Warp owns 4 words per e_v tile; private 3-stage cp.async ring;
// 2 static tiles/warp + atomic tail. After e_v tiles are exhausted a warp
// grabs (b,t) fixup tasks: computes exp(tanh(k*e_k)) into g_fix (scratch).
// ---------------------------------------------------------------------------
__global__ void __launch_bounds__(256, 3) ev_main_kernel(
    const float* __restrict__ gru,   // [B, H]
    const float* __restrict__ emb,   // [B, E]
    const float* __restrict__ ctx,   // [B, H]
    const int*   __restrict__ topic, // [B, T]
    int T,
    const float* __restrict__ W_V,   // [V, XV]
    const float* __restrict__ b_V,   // [V]
    const float* __restrict__ W_K,   // [V, XK]
    const float* __restrict__ b_K,   // [V]
    float* __restrict__ out)         // [B, V]
{
    extern __shared__ __align__(16) float dsm[];
    float* xs    = dsm;                                    // [8][1536]
    float* rings = dsm + BATCH * XV;                       // [8][DEPTH][STAGEF]
    float* rs    = rings + WARPS_PER_CTA * DEPTH * STAGEF; // [8]

    int tid = threadIdx.x;
    if (tid < BATCH) rs[tid] = 0.0f;
    for (int i = tid; i < BATCH * XV / 4; i += 256) {
        int idx = i * 4;
        int b = idx / XV;
        int c = idx - b * XV;
        float4 v;
        if (c < HDIM) v = *(const float4*)&gru[b * HDIM + c];
        else          v = *(const float4*)&emb[b * EDIM + (c - HDIM)];
        *(float4*)&xs[b * XV + c] = v;
    }
    __syncthreads();

    int warp  = tid >> 5;
    int lane  = tid & 31;
    int half  = lane >> 4;
    int l16   = lane & 15;
    int bbase = half * 4;
    int lc    = l16 * 4;
    int myb   = bbase + (l16 & 3);
    int gw    = blockIdx.x * WARPS_PER_CTA + warp;   // 0..3551
    float rsum = 0.0f;

    float* ring = rings + warp * (DEPTH * STAGEF);
    unsigned ring_s = (unsigned)__cvta_generic_to_shared(ring);

    int goff0, goff1;
    unsigned soff0, soff1;
    {
        int f0 = lane, f1 = lane + 32;
        goff0 = (f0 >> 4) * XV + (f0 & 15) * 4;
        goff1 = (f1 >> 4) * XV + (f1 & 15) * 4;
        soff0 = ((f0 >> 4) * 64 + (f0 & 15) * 4) * 4;
        soff1 = ((f1 >> 4) * 64 + (f1 & 15) * 4) * 4;
    }

    int t  = gw;                       // static tile 0
    int tn = gw + NWARPS_TOTAL;        // static tile 1 (< 7104, valid)
    const float* Wt = W_V + (size_t)t * (NW * XV);

#pragma unroll
    for (int s = 0; s < DEPTH; s++) {
        cp16s(ring_s + s * (STAGEF * 4) + soff0, Wt + s * 64 + goff0);
        cp16s(ring_s + s * (STAGEF * 4) + soff1, Wt + s * 64 + goff1);
        CP_COMMIT();
    }

    while (t < TILES) {
        const float* Wn = W_V + (size_t)tn * (NW * XV);
        bool nvalid  = tn < TILES;
        int  pend    = 0;
        if (nvalid && lane == 0)
            pend = STATIC_TILES + atomicAdd(&g_tile, 1);   // overlapped grab

        u64 acc[NW][4];
#pragma unroll
        for (int wi = 0; wi < NW; wi++)
#pragma unroll
            for (int bi = 0; bi < 4; bi++) acc[wi][bi] = 0ull;

#pragma unroll 3
        for (int c = 0; c < NSTAGES; c++) {
            CP_WAIT(DEPTH - 1);
            __syncwarp();

            const float* rg = ring + (c % DEPTH) * STAGEF;
            int xc = c * 64 + lc;
            ulonglong2 x0 = *(const ulonglong2*)&xs[(bbase + 0) * XV + xc];
            ulonglong2 x1 = *(const ulonglong2*)&xs[(bbase + 1) * XV + xc];
            ulonglong2 x2 = *(const ulonglong2*)&xs[(bbase + 2) * XV + xc];
            ulonglong2 x3 = *(const ulonglong2*)&xs[(bbase + 3) * XV + xc];

#pragma unroll
            for (int wi = 0; wi < NW; wi++) {
                ulonglong2 w = *(const ulonglong2*)&rg[wi * 64 + lc];
                acc[wi][0] = fma2(w.x, x0.x, acc[wi][0]);
                acc[wi][0] = fma2(w.y, x0.y, acc[wi][0]);
                acc[wi][1] = fma2(w.x, x1.x, acc[wi][1]);
                acc[wi][1] = fma2(w.y, x1.y, acc[wi][1]);
                acc[wi][2] = fma2(w.x, x2.x, acc[wi][2]);
                acc[wi][2] = fma2(w.y, x2.y, acc[wi][2]);
                acc[wi][3] = fma2(w.x, x3.x, acc[wi][3]);
                acc[wi][3] = fma2(w.y, x3.y, acc[wi][3]);
            }

            unsigned slot = ring_s + (c % DEPTH) * (STAGEF * 4);
            int cn = c + DEPTH;
            if (cn < NSTAGES) {
                cp16s(slot + soff0, Wt + cn * 64 + goff0);
                cp16s(slot + soff1, Wt + cn * 64 + goff1);
            } else if (nvalid) {
                int cc = cn - NSTAGES;
                cp16s(slot + soff0, Wn + cc * 64 + goff0);
                cp16s(slot + soff1, Wn + cc * 64 + goff1);
            }
            CP_COMMIT();
        }

        float v[16];
#pragma unroll
        for (int wi = 0; wi < NW; wi++)
#pragma unroll
            for (int bi = 0; bi < 4; bi++)
                v[wi * 4 + bi] = f2_lo(acc[wi][bi]) + f2_hi(acc[wi][bi]);
        float s0 = reduce16(v, l16);

        int word = t * NW + (l16 >> 2);
        float u  = exp_tanh(s0 + __ldg(&b_V[word]));
        out[(size_t)myb * VOCAB + word] = u;
        rsum += u;

        t  = tn;
        Wt = Wn;
        if (nvalid) {
            pend = __shfl_sync(0xffffffffu, pend, 0);
            tn = pend;
        } else {
            tn = TILES;
        }
    }

    // row-sum reduction before switching to fixup work
    atomicAdd(&rs[myb], rsum);

    // ---- fixup tasks: compute exp(tanh(k*e_k)) into scratch g_fix ----
    for (;;) {
        int f = 0;
        if (lane == 0) f = atomicAdd(&g_fixt, 1);
        f = __shfl_sync(0xffffffffu, f, 0);
        if (f >= BATCH * T) break;

        int b = f / T;
        int tt0 = f - b * T;
        int w = topic[b * T + tt0];
        float result = 0.0f;                 // 0 = invalid sentinel
        if (w != 0) {
            int cnt = 0, first = T;
            for (int tt = lane; tt < T; tt += 32) {
                if (topic[b * T + tt] == w) {
                    cnt += 1;
                    if (tt < first) first = tt;
                }
            }
#pragma unroll
            for (int o = 16; o > 0; o >>= 1) {
                cnt += __shfl_xor_sync(0xffffffffu, cnt, o);
                int of = __shfl_xor_sync(0xffffffffu, first, o);
                first = of < first ? of : first;
            }
            if (first == tt0) {              // this warp owns the word
                const float* Wr = W_K + (size_t)w * XK + lane * 4;
                const int cbase = lane * 4;
                float s = 0.0f;
#pragma unroll
                for (int j = 0; j < XK / 128; ++j) {   // 20 fixed iterations
                    int c = cbase + j * 128;
                    float4 wv = *(const float4*)&Wr[j * 128];
                    float4 xv;
                    if (c < HDIM)      xv = *(const float4*)&gru[b * HDIM + c];
                    else if (c < XV)   xv = *(const float4*)&emb[b * EDIM + (c - HDIM)];
                    else               xv = *(const float4*)&ctx[b * HDIM + (c - XV)];
                    s += wv.x * xv.x + wv.y * xv.y + wv.z * xv.z + wv.w * xv.w;
                }
#pragma unroll
                for (int o = 16; o > 0; o >>= 1)
                    s += __shfl_xor_sync(0xffffffffu, s, o);
                result = exp_tanh((float)cnt * (s + b_K[w]));
            }
        }
        if (lane == 0) g_fix[f] = result;    // every task slot written each launch
    }

    __syncthreads();
    if (tid < BATCH) atomicAdd(&g_rowsum[tid], rs[tid]);
}

// ---------------------------------------------------------------------------
// Kernel 2: apply fixups. 800 threads: swap g_fix values into out, adjust
// row sums by (new - old).
// ---------------------------------------------------------------------------
__global__ void __launch_bounds__(256) apply_kernel(
    const int* __restrict__ topic,   // [B, T]
    int T,
    float* __restrict__ out)
{
    int f = blockIdx.x * 256 + threadIdx.x;
    if (f >= BATCH * T) return;
    float nu = g_fix[f];
    if (nu == 0.0f) return;                  // invalid (pad or duplicate)
    int b = f / T;
    int w = topic[f];
    size_t ix = (size_t)b * VOCAB + w;
    float old = out[ix];
    out[ix] = nu;
    atomicAdd(&g_rowsum[b], nu - old);
}

// ---------------------------------------------------------------------------
// Kernel 3: scale by 1/rowsum; last CTA resets all device counters.
// ---------------------------------------------------------------------------
__global__ void __launch_bounds__(256) norm_kernel(float* __restrict__ out)
{
    int b     = blockIdx.x / NORM_SLICES;
    int slice = blockIdx.x % NORM_SLICES;
    float inv = 1.0f / g_rowsum[b];

    const int per = VOCAB / NORM_SLICES;          // 2000
    float* seg = out + (size_t)b * VOCAB + slice * per;
    for (int i = threadIdx.x * 4; i < per; i += 256 * 4) {
        float4 v = *(const float4*)&seg[i];
        v.x *= inv; v.y *= inv; v.z *= inv; v.w *= inv;
        *(float4*)&seg[i] = v;
    }

    __syncthreads();
    if (threadIdx.x == 0) {
        int d = atomicAdd(&g_norm_done, 1);
        if (d == NORM_GRID - 1) {
            for (int i = 0; i < BATCH; i++) g_rowsum[i] = 0.0f;
            g_tile = 0;
            g_fixt = 0;
            __threadfence();
            g_norm_done = 0;
        }
    }
}

// ---------------------------------------------------------------------------
extern "C" void kernel_launch(void* const* d_in, const int* in_sizes, int n_in,
                              void* d_out, int out_size)
{
    const float* gru   = (const float*)d_in[0];
    const float* emb   = (const float*)d_in[1];
    const float* ctx   = (const float*)d_in[2];
    const int*   topic = (const int*)d_in[3];
    int T = in_sizes[3] / BATCH;

    const float* W_V = nullptr; const float* b_V = nullptr;
    const float* W_K = nullptr; const float* b_K = nullptr;
    for (int i = 4; i < n_in; ++i) {
        long sz = (long)in_sizes[i];
        if (sz == (long)VOCAB * XV && i + 1 < n_in) {
            W_V = (const float*)d_in[i];
            b_V = (const float*)d_in[i + 1];
        } else if (sz == (long)VOCAB * XK && i + 1 < n_in) {
            W_K = (const float*)d_in[i];
            b_K = (const float*)d_in[i + 1];
        }
    }

    float* out = (float*)d_out;

    static bool attr_set = false;
    if (!attr_set) {
        cudaFuncSetAttribute(ev_main_kernel,
                             cudaFuncAttributeMaxDynamicSharedMemorySize,
                             SMEM_BYTES);
        attr_set = true;
    }

    ev_main_kernel<<<CTAS, 256, SMEM_BYTES>>>(
        gru, emb, ctx, topic, T, W_V, b_V, W_K, b_K, out);

    int bt = BATCH * T;
    apply_kernel<<<(bt + 255) / 256, 256>>>(topic, T, out);

    norm_kernel<<<NORM_GRID, 256>>>(out);
}

// round 11
// speedup vs baseline: 1.1372x; 1.1372x over previous
#include <cuda_runtime.h>
#include <math.h>

// Problem constants: B=8, H=1024, E=512, V=32000, T=100
#define VOCAB 32000
#define BATCH 8
#define HDIM  1024
#define EDIM  512
#define XV    (HDIM + EDIM)        // 1536
#define XK    (2 * HDIM + EDIM)    // 2560
#define TMAX  128

#define NW      4                  // words per tile
#define TILES   (VOCAB / NW)       // 8000
#define DEPTH   3                  // cp.async ring stages per warp
#define STAGEF  (NW * 64)          // floats per stage = 1KB
#define NSTAGES (XV / 64)          // 24 column-chunks
#define CTAS    444                // 148 SMs x 3 CTAs
#define WARPS_PER_CTA 8
#define NWARPS_TOTAL (CTAS * WARPS_PER_CTA)      // 3552
#define STATIC_TILES (2 * NWARPS_TOTAL)          // 7104 static; 896 tail
#define NORM_SLICES 16
#define NORM_GRID (BATCH * NORM_SLICES)

// dynamic smem: xs[8][1536] | rings[8 warps][DEPTH][STAGEF] | rs[8]
#define SMEM_FLOATS (BATCH * XV + WARPS_PER_CTA * DEPTH * STAGEF + 8)
#define SMEM_BYTES  (SMEM_FLOATS * 4)

typedef unsigned long long u64;

__device__ __forceinline__ u64 fma2(u64 a, u64 b, u64 c) {
    u64 d;
    asm("fma.rn.f32x2 %0, %1, %2, %3;" : "=l"(d) : "l"(a), "l"(b), "l"(c));
    return d;
}
__device__ __forceinline__ float f2_lo(u64 a) { return __uint_as_float((unsigned)a); }
__device__ __forceinline__ float f2_hi(u64 a) { return __uint_as_float((unsigned)(a >> 32)); }

__device__ __forceinline__ float exp_tanh(float e) {
    float ec = fminf(fmaxf(e, -9.0f), 9.0f);
    float t  = __expf(2.0f * ec);
    float th = (t - 1.0f) / (t + 1.0f);
    return __expf(th);
}

__device__ __forceinline__ void cp16s(unsigned saddr, const float* gmem_src) {
    asm volatile("cp.async.cg.shared.global [%0], [%1], 16;\n"
                 :: "r"(saddr), "l"(gmem_src) : "memory");
}
#define CP_COMMIT() asm volatile("cp.async.commit_group;\n" ::: "memory")
#define CP_WAIT(N)  asm volatile("cp.async.wait_group %0;\n" :: "n"(N) : "memory")

// device state (counters reset by norm kernel each launch -> replay safe)
__device__ int   g_tile = 0;                 // e_v tail counter
__device__ float g_rowsum[BATCH] = {};
__device__ int   g_norm_done = 0;
__device__ float g_fix[BATCH * TMAX];        // fixup results (0 = invalid);
                                             // fully rewritten every launch

// 16-value compacting butterfly across a half-warp. Lane l16 ends with index l16.
__device__ __forceinline__ float reduce16(float* v, int l16) {
#pragma unroll
    for (int d = 8; d > 0; d >>= 1) {
#pragma unroll
        for (int i = 0; i < 16; i++) {
            if (i < d) {
                float give = (l16 & d) ? v[i] : v[i + d];
                float got  = __shfl_xor_sync(0xffffffffu, give, d);
                float keep = (l16 & d) ? v[i + d] : v[i];
                v[i] = keep + got;
            }
        }
    }
    return v[0];
}

// ---------------------------------------------------------------------------
// Kernel A (runs FIRST, independent of main): compute fixup values into
// scratch. One warp per (b,t); first occurrence of each word computes
// exp(tanh(cnt * (x_k . W_K[w] + b_K[w]))), others write 0 (invalid).
// ---------------------------------------------------------------------------
__global__ void __launch_bounds__(256) fix_compute_kernel(
    const float* __restrict__ gru,
    const float* __restrict__ emb,
    const float* __restrict__ ctx,
    const int*   __restrict__ topic, // [B, T]
    int T,
    const float* __restrict__ W_K,   // [V, XK]
    const float* __restrict__ b_K,   // [V]
    float* __restrict__ out_unused)
{
    int gw   = (int)((blockIdx.x * blockDim.x + threadIdx.x) >> 5);
    int lane = threadIdx.x & 31;
    if (gw >= BATCH * T) return;
    int b = gw / T;
    int t = gw - b * T;

    int w = topic[b * T + t];
    float result = 0.0f;
    if (w != 0) {
        int cnt = 0, first = T;
        for (int tt = lane; tt < T; tt += 32) {
            if (topic[b * T + tt] == w) {
                cnt += 1;
                if (tt < first) first = tt;
            }
        }
#pragma unroll
        for (int o = 16; o > 0; o >>= 1) {
            cnt += __shfl_xor_sync(0xffffffffu, cnt, o);
            int of = __shfl_xor_sync(0xffffffffu, first, o);
            first = of < first ? of : first;
        }
        if (first == t) {
            const float* Wr = W_K + (size_t)w * XK + lane * 4;
            const int cbase = lane * 4;
            float s = 0.0f;
#pragma unroll
            for (int j = 0; j < XK / 128; ++j) {   // 20 fixed iterations
                int c = cbase + j * 128;
                float4 wv = *(const float4*)&Wr[j * 128];
                float4 xv;
                if (c < HDIM)      xv = *(const float4*)&gru[b * HDIM + c];
                else if (c < XV)   xv = *(const float4*)&emb[b * EDIM + (c - HDIM)];
                else               xv = *(const float4*)&ctx[b * HDIM + (c - XV)];
                s += wv.x * xv.x + wv.y * xv.y + wv.z * xv.z + wv.w * xv.w;
            }
#pragma unroll
            for (int o = 16; o > 0; o >>= 1)
                s += __shfl_xor_sync(0xffffffffu, s, o);
            result = exp_tanh((float)cnt * (s + b_K[w]));
        }
    }
    if (lane == 0) g_fix[gw] = result;
}

// ---------------------------------------------------------------------------
// Kernel B (main, EXACT R9 structure): e_v for ALL words.
// 3 CTAs/SM. Warp owns 4 words; private 3-stage cp.async ring; 2 static
// tiles/warp + atomic tail (grabbed one tile ahead).
// Lanes 0-15 accumulate batches 0-3, lanes 16-31 batches 4-7.
// ---------------------------------------------------------------------------
__global__ void __launch_bounds__(256, 3) ev_main_kernel(
    const float* __restrict__ gru,   // [B, H]
    const float* __restrict__ emb,   // [B, E]
    const float* __restrict__ W_V,   // [V, XV]
    const float* __restrict__ b_V,   // [V]
    float* __restrict__ out)         // [B, V]
{
    extern __shared__ __align__(16) float dsm[];
    float* xs    = dsm;                                    // [8][1536]
    float* rings = dsm + BATCH * XV;                       // [8][DEPTH][STAGEF]
    float* rs    = rings + WARPS_PER_CTA * DEPTH * STAGEF; // [8]

    int tid = threadIdx.x;
    if (tid < BATCH) rs[tid] = 0.0f;
    for (int i = tid; i < BATCH * XV / 4; i += 256) {
        int idx = i * 4;
        int b = idx / XV;
        int c = idx - b * XV;
        float4 v;
        if (c < HDIM) v = *(const float4*)&gru[b * HDIM + c];
        else          v = *(const float4*)&emb[b * EDIM + (c - HDIM)];
        *(float4*)&xs[b * XV + c] = v;
    }
    __syncthreads();

    int warp  = tid >> 5;
    int lane  = tid & 31;
    int half  = lane >> 4;
    int l16   = lane & 15;
    int bbase = half * 4;
    int lc    = l16 * 4;
    int myb   = bbase + (l16 & 3);
    int gw    = blockIdx.x * WARPS_PER_CTA + warp;   // 0..3551
    float rsum = 0.0f;

    float* ring = rings + warp * (DEPTH * STAGEF);
    unsigned ring_s = (unsigned)__cvta_generic_to_shared(ring);

    int goff0, goff1;
    unsigned soff0, soff1;
    {
        int f0 = lane, f1 = lane + 32;
        goff0 = (f0 >> 4) * XV + (f0 & 15) * 4;
        goff1 = (f1 >> 4) * XV + (f1 & 15) * 4;
        soff0 = ((f0 >> 4) * 64 + (f0 & 15) * 4) * 4;
        soff1 = ((f1 >> 4) * 64 + (f1 & 15) * 4) * 4;
    }

    int t  = gw;                       // static tile 0
    int tn = gw + NWARPS_TOTAL;        // static tile 1 (< 7104, valid)
    const float* Wt = W_V + (size_t)t * (NW * XV);

#pragma unroll
    for (int s = 0; s < DEPTH; s++) {
        cp16s(ring_s + s * (STAGEF * 4) + soff0, Wt + s * 64 + goff0);
        cp16s(ring_s + s * (STAGEF * 4) + soff1, Wt + s * 64 + goff1);
        CP_COMMIT();
    }

    while (t < TILES) {
        const float* Wn = W_V + (size_t)tn * (NW * XV);
        bool nvalid  = tn < TILES;
        int  pend    = 0;
        if (nvalid && lane == 0)
            pend = STATIC_TILES + atomicAdd(&g_tile, 1);   // overlapped grab

        u64 acc[NW][4];
#pragma unroll
        for (int wi = 0; wi < NW; wi++)
#pragma unroll
            for (int bi = 0; bi < 4; bi++) acc[wi][bi] = 0ull;

#pragma unroll 3
        for (int c = 0; c < NSTAGES; c++) {
            CP_WAIT(DEPTH - 1);
            __syncwarp();

            const float* rg = ring + (c % DEPTH) * STAGEF;
            int xc = c * 64 + lc;
            ulonglong2 x0 = *(const ulonglong2*)&xs[(bbase + 0) * XV + xc];
            ulonglong2 x1 = *(const ulonglong2*)&xs[(bbase + 1) * XV + xc];
            ulonglong2 x2 = *(const ulonglong2*)&xs[(bbase + 2) * XV + xc];
            ulonglong2 x3 = *(const ulonglong2*)&xs[(bbase + 3) * XV + xc];

#pragma unroll
            for (int wi = 0; wi < NW; wi++) {
                ulonglong2 w = *(const ulonglong2*)&rg[wi * 64 + lc];
                acc[wi][0] = fma2(w.x, x0.x, acc[wi][0]);
                acc[wi][0] = fma2(w.y, x0.y, acc[wi][0]);
                acc[wi][1] = fma2(w.x, x1.x, acc[wi][1]);
                acc[wi][1] = fma2(w.y, x1.y, acc[wi][1]);
                acc[wi][2] = fma2(w.x, x2.x, acc[wi][2]);
                acc[wi][2] = fma2(w.y, x2.y, acc[wi][2]);
                acc[wi][3] = fma2(w.x, x3.x, acc[wi][3]);
                acc[wi][3] = fma2(w.y, x3.y, acc[wi][3]);
            }

            unsigned slot = ring_s + (c % DEPTH) * (STAGEF * 4);
            int cn = c + DEPTH;
            if (cn < NSTAGES) {
                cp16s(slot + soff0, Wt + cn * 64 + goff0);
                cp16s(slot + soff1, Wt + cn * 64 + goff1);
            } else if (nvalid) {
                int cc = cn - NSTAGES;
                cp16s(slot + soff0, Wn + cc * 64 + goff0);
                cp16s(slot + soff1, Wn + cc * 64 + goff1);
            }
            CP_COMMIT();
        }

        float v[16];
#pragma unroll
        for (int wi = 0; wi < NW; wi++)
#pragma unroll
            for (int bi = 0; bi < 4; bi++)
                v[wi * 4 + bi] = f2_lo(acc[wi][bi]) + f2_hi(acc[wi][bi]);
        float s0 = reduce16(v, l16);

        int word = t * NW + (l16 >> 2);
        float u  = exp_tanh(s0 + __ldg(&b_V[word]));
        out[(size_t)myb * VOCAB + word] = u;
        rsum += u;

        t  = tn;
        Wt = Wn;
        if (nvalid) {
            pend = __shfl_sync(0xffffffffu, pend, 0);
            tn = pend;
        } else {
            tn = TILES;
        }
    }

    atomicAdd(&rs[myb], rsum);
    __syncthreads();
    if (tid < BATCH) atomicAdd(&g_rowsum[tid], rs[tid]);
}

// ---------------------------------------------------------------------------
// Kernel C: apply fixups. 800 threads: swap g_fix values into out, adjust
// row sums by (new - old).
// ---------------------------------------------------------------------------
__global__ void __launch_bounds__(256) apply_kernel(
    const int* __restrict__ topic,   // [B, T]
    int T,
    float* __restrict__ out)
{
    int f = blockIdx.x * 256 + threadIdx.x;
    if (f >= BATCH * T) return;
    float nu = g_fix[f];
    if (nu == 0.0f) return;                  // invalid (pad or duplicate)
    int b = f / T;
    int w = topic[f];
    size_t ix = (size_t)b * VOCAB + w;
    float old = out[ix];
    out[ix] = nu;
    atomicAdd(&g_rowsum[b], nu - old);
}

// ---------------------------------------------------------------------------
// Kernel D: scale by 1/rowsum; last CTA resets all device counters.
// ---------------------------------------------------------------------------
__global__ void __launch_bounds__(256) norm_kernel(float* __restrict__ out)
{
    int b     = blockIdx.x / NORM_SLICES;
    int slice = blockIdx.x % NORM_SLICES;
    float inv = 1.0f / g_rowsum[b];

    const int per = VOCAB / NORM_SLICES;          // 2000
    float* seg = out + (size_t)b * VOCAB + slice * per;
    for (int i = threadIdx.x * 4; i < per; i += 256 * 4) {
        float4 v = *(const float4*)&seg[i];
        v.x *= inv; v.y *= inv; v.z *= inv; v.w *= inv;
        *(float4*)&seg[i] = v;
    }

    __syncthreads();
    if (threadIdx.x == 0) {
        int d = atomicAdd(&g_norm_done, 1);
        if (d == NORM_GRID - 1) {
            for (int i = 0; i < BATCH; i++) g_rowsum[i] = 0.0f;
            g_tile = 0;
            __threadfence();
            g_norm_done = 0;
        }
    }
}

// ---------------------------------------------------------------------------
extern "C" void kernel_launch(void* const* d_in, const int* in_sizes, int n_in,
                              void* d_out, int out_size)
{
    const float* gru   = (const float*)d_in[0];
    const float* emb   = (const float*)d_in[1];
    const float* ctx   = (const float*)d_in[2];
    const int*   topic = (const int*)d_in[3];
    int T = in_sizes[3] / BATCH;

    const float* W_V = nullptr; const float* b_V = nullptr;
    const float* W_K = nullptr; const float* b_K = nullptr;
    for (int i = 4; i < n_in; ++i) {
        long sz = (long)in_sizes[i];
        if (sz == (long)VOCAB * XV && i + 1 < n_in) {
            W_V = (const float*)d_in[i];
            b_V = (const float*)d_in[i + 1];
        } else if (sz == (long)VOCAB * XK && i + 1 < n_in) {
            W_K = (const float*)d_in[i];
            b_K = (const float*)d_in[i + 1];
        }
    }

    float* out = (float*)d_out;

    static bool attr_set = false;
    if (!attr_set) {
        cudaFuncSetAttribute(ev_main_kernel,
                             cudaFuncAttributeMaxDynamicSharedMemorySize,
                             SMEM_BYTES);
        attr_set = true;
    }

    // A: fixup values into scratch (independent of main; runs first)
    int bt = BATCH * T;
    int fb = (bt * 32 + 255) / 256;
    fix_compute_kernel<<<fb, 256>>>(gru, emb, ctx, topic, T, W_K, b_K, out);

    // B: main e_v GEMM + row sums
    ev_main_kernel<<<CTAS, 256, SMEM_BYTES>>>(gru, emb, W_V, b_V, out);

    // C: apply fixups into out (+ rowsum deltas)
    apply_kernel<<<(bt + 255) / 256, 256>>>(topic, T, out);

    // D: normalize + reset counters
    norm_kernel<<<NORM_GRID, 256>>>(out);
}

// round 12
// speedup vs baseline: 1.1543x; 1.0150x over previous
#include <cuda_runtime.h>
#include <math.h>

// Problem constants: B=8, H=1024, E=512, V=32000, T=100
#define VOCAB 32000
#define BATCH 8
#define HDIM  1024
#define EDIM  512
#define XV    (HDIM + EDIM)        // 1536
#define XK    (2 * HDIM + EDIM)    // 2560

#define NW      4                  // words per tile
#define TILES   (VOCAB / NW)       // 8000
#define DEPTH   3                  // cp.async ring stages per warp
#define STAGEF  (NW * 64)          // floats per stage = 1KB
#define NSTAGES (XV / 64)          // 24 column-chunks
#define CTAS    444                // 148 SMs x 3 CTAs
#define WARPS_PER_CTA 8
#define NWARPS_TOTAL (CTAS * WARPS_PER_CTA)      // 3552
#define STATIC_TILES (2 * NWARPS_TOTAL)          // 7104 static; 896 tail
#define NORM_GRID 250              // 250 x 256 threads = 64000 = VOCAB*BATCH/4

// dynamic smem: xs[8][1536] | rings[8 warps][DEPTH][STAGEF] | rs[8]
#define SMEM_FLOATS (BATCH * XV + WARPS_PER_CTA * DEPTH * STAGEF + 8)
#define SMEM_BYTES  (SMEM_FLOATS * 4)

typedef unsigned long long u64;

__device__ __forceinline__ u64 fma2(u64 a, u64 b, u64 c) {
    u64 d;
    asm("fma.rn.f32x2 %0, %1, %2, %3;" : "=l"(d) : "l"(a), "l"(b), "l"(c));
    return d;
}
__device__ __forceinline__ float f2_lo(u64 a) { return __uint_as_float((unsigned)a); }
__device__ __forceinline__ float f2_hi(u64 a) { return __uint_as_float((unsigned)(a >> 32)); }

__device__ __forceinline__ float exp_tanh(float e) {
    float ec = fminf(fmaxf(e, -9.0f), 9.0f);
    float t  = __expf(2.0f * ec);
    float th = (t - 1.0f) / (t + 1.0f);
    return __expf(th);
}

__device__ __forceinline__ void cp16s(unsigned saddr, const float* gmem_src) {
    asm volatile("cp.async.cg.shared.global [%0], [%1], 16;\n"
                 :: "r"(saddr), "l"(gmem_src) : "memory");
}
#define CP_COMMIT() asm volatile("cp.async.commit_group;\n" ::: "memory")
#define CP_WAIT(N)  asm volatile("cp.async.wait_group %0;\n" :: "n"(N) : "memory")

// device state (counters reset by norm kernel each launch -> replay safe)
__device__ int   g_tile = 0;                 // e_v tail counter
__device__ float g_rowsum[BATCH] = {};
__device__ int   g_norm_done = 0;

// 16-value compacting butterfly across a half-warp. Lane l16 ends with index l16.
__device__ __forceinline__ float reduce16(float* v, int l16) {
#pragma unroll
    for (int d = 8; d > 0; d >>= 1) {
#pragma unroll
        for (int i = 0; i < 16; i++) {
            if (i < d) {
                float give = (l16 & d) ? v[i] : v[i + d];
                float got  = __shfl_xor_sync(0xffffffffu, give, d);
                float keep = (l16 & d) ? v[i + d] : v[i];
                v[i] = keep + got;
            }
        }
    }
    return v[0];
}

// ---------------------------------------------------------------------------
// Kernel 1 (main, EXACT R9/R11 structure — do not touch): e_v for ALL words.
// 3 CTAs/SM. Warp owns 4 words; private 3-stage cp.async ring; 2 static
// tiles/warp + atomic tail (grabbed one tile ahead).
// Lanes 0-15 accumulate batches 0-3, lanes 16-31 batches 4-7.
// ---------------------------------------------------------------------------
__global__ void __launch_bounds__(256, 3) ev_main_kernel(
    const float* __restrict__ gru,   // [B, H]
    const float* __restrict__ emb,   // [B, E]
    const float* __restrict__ W_V,   // [V, XV]
    const float* __restrict__ b_V,   // [V]
    float* __restrict__ out)         // [B, V]
{
    extern __shared__ __align__(16) float dsm[];
    float* xs    = dsm;                                    // [8][1536]
    float* rings = dsm + BATCH * XV;                       // [8][DEPTH][STAGEF]
    float* rs    = rings + WARPS_PER_CTA * DEPTH * STAGEF; // [8]

    int tid = threadIdx.x;
    if (tid < BATCH) rs[tid] = 0.0f;
    for (int i = tid; i < BATCH * XV / 4; i += 256) {
        int idx = i * 4;
        int b = idx / XV;
        int c = idx - b * XV;
        float4 v;
        if (c < HDIM) v = *(const float4*)&gru[b * HDIM + c];
        else          v = *(const float4*)&emb[b * EDIM + (c - HDIM)];
        *(float4*)&xs[b * XV + c] = v;
    }
    __syncthreads();

    int warp  = tid >> 5;
    int lane  = tid & 31;
    int half  = lane >> 4;
    int l16   = lane & 15;
    int bbase = half * 4;
    int lc    = l16 * 4;
    int myb   = bbase + (l16 & 3);
    int gw    = blockIdx.x * WARPS_PER_CTA + warp;   // 0..3551
    float rsum = 0.0f;

    float* ring = rings + warp * (DEPTH * STAGEF);
    unsigned ring_s = (unsigned)__cvta_generic_to_shared(ring);

    int goff0, goff1;
    unsigned soff0, soff1;
    {
        int f0 = lane, f1 = lane + 32;
        goff0 = (f0 >> 4) * XV + (f0 & 15) * 4;
        goff1 = (f1 >> 4) * XV + (f1 & 15) * 4;
        soff0 = ((f0 >> 4) * 64 + (f0 & 15) * 4) * 4;
        soff1 = ((f1 >> 4) * 64 + (f1 & 15) * 4) * 4;
    }

    int t  = gw;                       // static tile 0
    int tn = gw + NWARPS_TOTAL;        // static tile 1 (< 7104, valid)
    const float* Wt = W_V + (size_t)t * (NW * XV);

#pragma unroll
    for (int s = 0; s < DEPTH; s++) {
        cp16s(ring_s + s * (STAGEF * 4) + soff0, Wt + s * 64 + goff0);
        cp16s(ring_s + s * (STAGEF * 4) + soff1, Wt + s * 64 + goff1);
        CP_COMMIT();
    }

    while (t < TILES) {
        const float* Wn = W_V + (size_t)tn * (NW * XV);
        bool nvalid  = tn < TILES;
        int  pend    = 0;
        if (nvalid && lane == 0)
            pend = STATIC_TILES + atomicAdd(&g_tile, 1);   // overlapped grab

        u64 acc[NW][4];
#pragma unroll
        for (int wi = 0; wi < NW; wi++)
#pragma unroll
            for (int bi = 0; bi < 4; bi++) acc[wi][bi] = 0ull;

#pragma unroll 3
        for (int c = 0; c < NSTAGES; c++) {
            CP_WAIT(DEPTH - 1);
            __syncwarp();

            const float* rg = ring + (c % DEPTH) * STAGEF;
            int xc = c * 64 + lc;
            ulonglong2 x0 = *(const ulonglong2*)&xs[(bbase + 0) * XV + xc];
            ulonglong2 x1 = *(const ulonglong2*)&xs[(bbase + 1) * XV + xc];
            ulonglong2 x2 = *(const ulonglong2*)&xs[(bbase + 2) * XV + xc];
            ulonglong2 x3 = *(const ulonglong2*)&xs[(bbase + 3) * XV + xc];

#pragma unroll
            for (int wi = 0; wi < NW; wi++) {
                ulonglong2 w = *(const ulonglong2*)&rg[wi * 64 + lc];
                acc[wi][0] = fma2(w.x, x0.x, acc[wi][0]);
                acc[wi][0] = fma2(w.y, x0.y, acc[wi][0]);
                acc[wi][1] = fma2(w.x, x1.x, acc[wi][1]);
                acc[wi][1] = fma2(w.y, x1.y, acc[wi][1]);
                acc[wi][2] = fma2(w.x, x2.x, acc[wi][2]);
                acc[wi][2] = fma2(w.y, x2.y, acc[wi][2]);
                acc[wi][3] = fma2(w.x, x3.x, acc[wi][3]);
                acc[wi][3] = fma2(w.y, x3.y, acc[wi][3]);
            }

            unsigned slot = ring_s + (c % DEPTH) * (STAGEF * 4);
            int cn = c + DEPTH;
            if (cn < NSTAGES) {
                cp16s(slot + soff0, Wt + cn * 64 + goff0);
                cp16s(slot + soff1, Wt + cn * 64 + goff1);
            } else if (nvalid) {
                int cc = cn - NSTAGES;
                cp16s(slot + soff0, Wn + cc * 64 + goff0);
                cp16s(slot + soff1, Wn + cc * 64 + goff1);
            }
            CP_COMMIT();
        }

        float v[16];
#pragma unroll
        for (int wi = 0; wi < NW; wi++)
#pragma unroll
            for (int bi = 0; bi < 4; bi++)
                v[wi * 4 + bi] = f2_lo(acc[wi][bi]) + f2_hi(acc[wi][bi]);
        float s0 = reduce16(v, l16);

        int word = t * NW + (l16 >> 2);
        float u  = exp_tanh(s0 + __ldg(&b_V[word]));
        out[(size_t)myb * VOCAB + word] = u;
        rsum += u;

        t  = tn;
        Wt = Wn;
        if (nvalid) {
            pend = __shfl_sync(0xffffffffu, pend, 0);
            tn = pend;
        } else {
            tn = TILES;
        }
    }

    atomicAdd(&rs[myb], rsum);
    __syncthreads();
    if (tid < BATCH) atomicAdd(&g_rowsum[tid], rs[tid]);
}

// ---------------------------------------------------------------------------
// Kernel 2: fused fixup (compute + dedup + apply). Runs after main.
// One warp per (b,t): first occurrence of each word computes
// exp(tanh(cnt*(x_k.W_K[w]+b_K[w]))), overwrites out, adjusts row sum.
// 200 CTAs x 128 threads for fast spread.
// ---------------------------------------------------------------------------
__global__ void __launch_bounds__(128) ek_fixup_kernel(
    const float* __restrict__ gru,
    const float* __restrict__ emb,
    const float* __restrict__ ctx,
    const int*   __restrict__ topic, // [B, T]
    int T,
    const float* __restrict__ W_K,   // [V, XK]
    const float* __restrict__ b_K,   // [V]
    float* __restrict__ out)
{
    int gw   = (int)((blockIdx.x * blockDim.x + threadIdx.x) >> 5);
    int lane = threadIdx.x & 31;
    if (gw >= BATCH * T) return;
    int b = gw / T;
    int t = gw - b * T;

    int w = topic[b * T + t];
    if (w == 0) return;

    int cnt = 0, first = T;
    for (int tt = lane; tt < T; tt += 32) {
        if (topic[b * T + tt] == w) {
            cnt += 1;
            if (tt < first) first = tt;
        }
    }
#pragma unroll
    for (int o = 16; o > 0; o >>= 1) {
        cnt += __shfl_xor_sync(0xffffffffu, cnt, o);
        int of = __shfl_xor_sync(0xffffffffu, first, o);
        first = of < first ? of : first;
    }
    if (first != t) return;              // another warp owns this word

    const float* Wr = W_K + (size_t)w * XK + lane * 4;
    const int cbase = lane * 4;
    float s = 0.0f;
#pragma unroll
    for (int j = 0; j < XK / 128; ++j) {            // 20 fixed iterations
        int c = cbase + j * 128;
        float4 wv = *(const float4*)&Wr[j * 128];
        float4 xv;
        if (c < HDIM)      xv = *(const float4*)&gru[b * HDIM + c];
        else if (c < XV)   xv = *(const float4*)&emb[b * EDIM + (c - HDIM)];
        else               xv = *(const float4*)&ctx[b * HDIM + (c - XV)];
        s += wv.x * xv.x + wv.y * xv.y + wv.z * xv.z + wv.w * xv.w;
    }
#pragma unroll
    for (int o = 16; o > 0; o >>= 1)
        s += __shfl_xor_sync(0xffffffffu, s, o);

    if (lane == 0) {
        float e   = (float)cnt * (s + b_K[w]);
        float nu  = exp_tanh(e);
        size_t ix = (size_t)b * VOCAB + w;
        float old = out[ix];
        out[ix] = nu;
        atomicAdd(&g_rowsum[b], nu - old);
    }
}

// ---------------------------------------------------------------------------
// Kernel 3: normalize. Exactly one float4 per thread (250x256 = 64000).
// Minimal chain: load inv (L2 broadcast), load, mul, store.
// Last-done CTA resets all counters for the next graph replay.
// ---------------------------------------------------------------------------
__global__ void __launch_bounds__(256) norm_kernel(float* __restrict__ out)
{
    int i = blockIdx.x * 256 + threadIdx.x;      // 0..63999 float4 index
    int b = i / (VOCAB / 4);                     // row (8000 float4 per row)
    float inv = 1.0f / g_rowsum[b];

    float4 v = ((const float4*)out)[i];
    v.x *= inv; v.y *= inv; v.z *= inv; v.w *= inv;
    ((float4*)out)[i] = v;

    __syncthreads();
    if (threadIdx.x == 0) {
        int d = atomicAdd(&g_norm_done, 1);
        if (d == NORM_GRID - 1) {
            for (int j = 0; j < BATCH; j++) g_rowsum[j] = 0.0f;
            g_tile = 0;
            __threadfence();
            g_norm_done = 0;
        }
    }
}

// ---------------------------------------------------------------------------
extern "C" void kernel_launch(void* const* d_in, const int* in_sizes, int n_in,
                              void* d_out, int out_size)
{
    const float* gru   = (const float*)d_in[0];
    const float* emb   = (const float*)d_in[1];
    const float* ctx   = (const float*)d_in[2];
    const int*   topic = (const int*)d_in[3];
    int T = in_sizes[3] / BATCH;

    const float* W_V = nullptr; const float* b_V = nullptr;
    const float* W_K = nullptr; const float* b_K = nullptr;
    for (int i = 4; i < n_in; ++i) {
        long sz = (long)in_sizes[i];
        if (sz == (long)VOCAB * XV && i + 1 < n_in) {
            W_V = (const float*)d_in[i];
            b_V = (const float*)d_in[i + 1];
        } else if (sz == (long)VOCAB * XK && i + 1 < n_in) {
            W_K = (const float*)d_in[i];
            b_K = (const float*)d_in[i + 1];
        }
    }

    float* out = (float*)d_out;

    static bool attr_set = false;
    if (!attr_set) {
        cudaFuncSetAttribute(ev_main_kernel,
                             cudaFuncAttributeMaxDynamicSharedMemorySize,
                             SMEM_BYTES);
        attr_set = true;
    }

    // 1) main e_v GEMM + row sums
    ev_main_kernel<<<CTAS, 256, SMEM_BYTES>>>(gru, emb, W_V, b_V, out);

    // 2) fused fixup: compute + dedup + apply + rowsum delta
    int nwarps  = BATCH * T;                      // 800
    int nblocks = (nwarps * 32 + 127) / 128;      // 200 CTAs
    ek_fixup_kernel<<<nblocks, 128>>>(gru, emb, ctx, topic, T, W_K, b_K, out);

    // 3) normalize + reset counters
    norm_kernel<<<NORM_GRID, 256>>>(out);
}

// round 13
// speedup vs baseline: 1.2430x; 1.0768x over previous
#include <cuda_runtime.h>
#include <math.h>

// Problem constants: B=8, H=1024, E=512, V=32000, T=100
#define VOCAB 32000
#define BATCH 8
#define HDIM  1024
#define EDIM  512
#define XV    (HDIM + EDIM)        // 1536
#define XK    (2 * HDIM + EDIM)    // 2560

#define NW      4                  // words per tile
#define TILES   (VOCAB / NW)       // 8000
#define DEPTH   6                  // cp.async ring stages per warp
#define STAGEF  (NW * 64)          // floats per stage = 1KB
#define NSTAGES (XV / 64)          // 24 column-chunks
#define CTAS    296                // 148 SMs x 2 CTAs
#define WARPS_PER_CTA 8
#define NWARPS_TOTAL (CTAS * WARPS_PER_CTA)   // 2368
#define NORM_GRID 250              // 250 x 256 = 64000 threads = VOCAB*BATCH/4

// dynamic smem: xs[8][1536] | rings[8 warps][DEPTH][STAGEF] | rs[8]
#define SMEM_FLOATS (BATCH * XV + WARPS_PER_CTA * DEPTH * STAGEF + 8)
#define SMEM_BYTES  (SMEM_FLOATS * 4)

typedef unsigned long long u64;

__device__ __forceinline__ u64 fma2(u64 a, u64 b, u64 c) {
    u64 d;
    asm("fma.rn.f32x2 %0, %1, %2, %3;" : "=l"(d) : "l"(a), "l"(b), "l"(c));
    return d;
}
__device__ __forceinline__ float f2_lo(u64 a) { return __uint_as_float((unsigned)a); }
__device__ __forceinline__ float f2_hi(u64 a) { return __uint_as_float((unsigned)(a >> 32)); }

__device__ __forceinline__ float exp_tanh(float e) {
    float ec = fminf(fmaxf(e, -9.0f), 9.0f);
    float t  = __expf(2.0f * ec);
    float th = (t - 1.0f) / (t + 1.0f);
    return __expf(th);
}

__device__ __forceinline__ void cp16(float* smem_dst, const float* gmem_src) {
    unsigned s = (unsigned)__cvta_generic_to_shared(smem_dst);
    asm volatile("cp.async.cg.shared.global [%0], [%1], 16;\n"
                 :: "r"(s), "l"(gmem_src) : "memory");
}
#define CP_COMMIT() asm volatile("cp.async.commit_group;\n" ::: "memory")
#define CP_WAIT(N)  asm volatile("cp.async.wait_group %0;\n" :: "n"(N) : "memory")

// device state (reset by norm kernel each launch -> graph-replay safe)
__device__ float g_rowsum[BATCH] = {};
__device__ int   g_norm_done = 0;

// 16-value compacting butterfly across a half-warp. Lane l16 ends with index l16.
__device__ __forceinline__ float reduce16(float* v, int l16) {
#pragma unroll
    for (int d = 8; d > 0; d >>= 1) {
#pragma unroll
        for (int i = 0; i < 16; i++) {
            if (i < d) {
                float give = (l16 & d) ? v[i] : v[i + d];
                float got  = __shfl_xor_sync(0xffffffffu, give, d);
                float keep = (l16 & d) ? v[i + d] : v[i];
                v[i] = keep + got;
            }
        }
    }
    return v[0];
}

// ---------------------------------------------------------------------------
// Kernel 1 (main — R8 configuration, best measured: 43.8us @ 57.9% DRAM):
// e_v for ALL words: out[b][w] = exp(tanh(x_v[b].W_V[w] + b_V[w]))
// 2 CTAs/SM, 124 regs. STATIC cyclic tile schedule (zero scheduling atomics).
// Warp owns 4 words, private 6-stage cp.async ring, no CTA barriers in
// steady state. Lanes 0-15 accumulate batches 0-3, lanes 16-31 batches 4-7.
// ---------------------------------------------------------------------------
__global__ void __launch_bounds__(256, 2) ev_main_kernel(
    const float* __restrict__ gru,   // [B, H]
    const float* __restrict__ emb,   // [B, E]
    const float* __restrict__ W_V,   // [V, XV]
    const float* __restrict__ b_V,   // [V]
    float* __restrict__ out)         // [B, V]
{
    extern __shared__ __align__(16) float dsm[];
    float* xs    = dsm;                                    // [8][1536]
    float* rings = dsm + BATCH * XV;                       // [8][DEPTH][STAGEF]
    float* rs    = rings + WARPS_PER_CTA * DEPTH * STAGEF; // [8]

    int tid = threadIdx.x;
    if (tid < BATCH) rs[tid] = 0.0f;
    for (int i = tid; i < BATCH * XV / 4; i += 256) {
        int idx = i * 4;
        int b = idx / XV;
        int c = idx - b * XV;
        float4 v;
        if (c < HDIM) v = *(const float4*)&gru[b * HDIM + c];
        else          v = *(const float4*)&emb[b * EDIM + (c - HDIM)];
        *(float4*)&xs[b * XV + c] = v;
    }
    __syncthreads();

    int warp  = tid >> 5;
    int lane  = tid & 31;
    int half  = lane >> 4;
    int l16   = lane & 15;
    int bbase = half * 4;
    int lc    = l16 * 4;
    int myb   = bbase + (l16 & 3);
    int gw    = blockIdx.x * WARPS_PER_CTA + warp;   // 0..2367
    float rsum = 0.0f;

    float* ring = rings + warp * (DEPTH * STAGEF);

    // per-lane cp.async offsets: 2 x 16B per stage (4 words x 16 float4)
    int goff[2], soff[2];
#pragma unroll
    for (int j = 0; j < 2; j++) {
        int f    = lane + 32 * j;
        int word = f >> 4;        // 0..3
        int col4 = f & 15;        // 0..15
        goff[j] = word * XV + col4 * 4;   // + chunk*64 at use site
        soff[j] = word * 64 + col4 * 4;
    }

    int t = gw;
    const float* Wt = W_V + (size_t)t * (NW * XV);

    // prologue: fill DEPTH stages from first tile (guarded)
#pragma unroll
    for (int s = 0; s < DEPTH; s++) {
        if (t < TILES) {
#pragma unroll
            for (int j = 0; j < 2; j++)
                cp16(ring + s * STAGEF + soff[j], Wt + s * 64 + goff[j]);
        }
        CP_COMMIT();
    }

    while (t < TILES) {
        int tn = t + NWARPS_TOTAL;                    // statically known
        const float* Wn = W_V + (size_t)tn * (NW * XV);
        bool nvalid = tn < TILES;

        u64 acc[NW][4];
#pragma unroll
        for (int wi = 0; wi < NW; wi++)
#pragma unroll
            for (int bi = 0; bi < 4; bi++) acc[wi][bi] = 0ull;

#pragma unroll 12
        for (int c = 0; c < NSTAGES; c++) {
            CP_WAIT(DEPTH - 1);
            __syncwarp();

            const float* rg = ring + (c % DEPTH) * STAGEF;
            int xc = c * 64 + lc;
            ulonglong2 x0 = *(const ulonglong2*)&xs[(bbase + 0) * XV + xc];
            ulonglong2 x1 = *(const ulonglong2*)&xs[(bbase + 1) * XV + xc];
            ulonglong2 x2 = *(const ulonglong2*)&xs[(bbase + 2) * XV + xc];
            ulonglong2 x3 = *(const ulonglong2*)&xs[(bbase + 3) * XV + xc];

#pragma unroll
            for (int wi = 0; wi < NW; wi++) {
                ulonglong2 w = *(const ulonglong2*)&rg[wi * 64 + lc];
                acc[wi][0] = fma2(w.x, x0.x, acc[wi][0]);
                acc[wi][0] = fma2(w.y, x0.y, acc[wi][0]);
                acc[wi][1] = fma2(w.x, x1.x, acc[wi][1]);
                acc[wi][1] = fma2(w.y, x1.y, acc[wi][1]);
                acc[wi][2] = fma2(w.x, x2.x, acc[wi][2]);
                acc[wi][2] = fma2(w.y, x2.y, acc[wi][2]);
                acc[wi][3] = fma2(w.x, x3.x, acc[wi][3]);
                acc[wi][3] = fma2(w.y, x3.y, acc[wi][3]);
            }

            // refill the just-consumed slot with chunk c+DEPTH (this tile or next)
            int cn = c + DEPTH;
            if (cn < NSTAGES) {
#pragma unroll
                for (int j = 0; j < 2; j++)
                    cp16(ring + (c % DEPTH) * STAGEF + soff[j],
                         Wt + cn * 64 + goff[j]);
            } else if (nvalid) {
                int cc = cn - NSTAGES;
#pragma unroll
                for (int j = 0; j < 2; j++)
                    cp16(ring + (c % DEPTH) * STAGEF + soff[j],
                         Wn + cc * 64 + goff[j]);
            }
            CP_COMMIT();
        }

        // epilogue: fold f32x2 pairs, one 16-value compaction per half-warp
        float v[16];
#pragma unroll
        for (int wi = 0; wi < NW; wi++)
#pragma unroll
            for (int bi = 0; bi < 4; bi++)
                v[wi * 4 + bi] = f2_lo(acc[wi][bi]) + f2_hi(acc[wi][bi]);
        float s0 = reduce16(v, l16);     // word t*4+(l16>>2), batch bbase+(l16&3)

        int word = t * NW + (l16 >> 2);
        float u  = exp_tanh(s0 + __ldg(&b_V[word]));
        out[(size_t)myb * VOCAB + word] = u;
        rsum += u;

        t  = tn;
        Wt = Wn;
    }

    // per-CTA row-sum reduction -> 8 global atomics
    atomicAdd(&rs[myb], rsum);
    __syncthreads();
    if (tid < BATCH) atomicAdd(&g_rowsum[tid], rs[tid]);
}

// ---------------------------------------------------------------------------
// Kernel 2: fused fixup (compute + dedup + apply). Runs after main.
// One warp per (b,t): first occurrence of each word computes
// exp(tanh(cnt*(x_k.W_K[w]+b_K[w]))), overwrites out, adjusts row sum.
// 200 CTAs x 128 threads.
// ---------------------------------------------------------------------------
__global__ void __launch_bounds__(128) ek_fixup_kernel(
    const float* __restrict__ gru,
    const float* __restrict__ emb,
    const float* __restrict__ ctx,
    const int*   __restrict__ topic, // [B, T]
    int T,
    const float* __restrict__ W_K,   // [V, XK]
    const float* __restrict__ b_K,   // [V]
    float* __restrict__ out)
{
    int gw   = (int)((blockIdx.x * blockDim.x + threadIdx.x) >> 5);
    int lane = threadIdx.x & 31;
    if (gw >= BATCH * T) return;
    int b = gw / T;
    int t = gw - b * T;

    int w = topic[b * T + t];
    if (w == 0) return;

    int cnt = 0, first = T;
    for (int tt = lane; tt < T; tt += 32) {
        if (topic[b * T + tt] == w) {
            cnt += 1;
            if (tt < first) first = tt;
        }
    }
#pragma unroll
    for (int o = 16; o > 0; o >>= 1) {
        cnt += __shfl_xor_sync(0xffffffffu, cnt, o);
        int of = __shfl_xor_sync(0xffffffffu, first, o);
        first = of < first ? of : first;
    }
    if (first != t) return;              // another warp owns this word

    const float* Wr = W_K + (size_t)w * XK + lane * 4;
    const int cbase = lane * 4;
    float s = 0.0f;
#pragma unroll
    for (int j = 0; j < XK / 128; ++j) {            // 20 fixed iterations
        int c = cbase + j * 128;
        float4 wv = *(const float4*)&Wr[j * 128];
        float4 xv;
        if (c < HDIM)      xv = *(const float4*)&gru[b * HDIM + c];
        else if (c < XV)   xv = *(const float4*)&emb[b * EDIM + (c - HDIM)];
        else               xv = *(const float4*)&ctx[b * HDIM + (c - XV)];
        s += wv.x * xv.x + wv.y * xv.y + wv.z * xv.z + wv.w * xv.w;
    }
#pragma unroll
    for (int o = 16; o > 0; o >>= 1)
        s += __shfl_xor_sync(0xffffffffu, s, o);

    if (lane == 0) {
        float e   = (float)cnt * (s + b_K[w]);
        float nu  = exp_tanh(e);
        size_t ix = (size_t)b * VOCAB + w;
        float old = out[ix];
        out[ix] = nu;
        atomicAdd(&g_rowsum[b], nu - old);
    }
}

// ---------------------------------------------------------------------------
// Kernel 3: normalize. Exactly one float4 per thread (250x256 = 64000).
// Last-done CTA resets counters for the next graph replay.
// ---------------------------------------------------------------------------
__global__ void __launch_bounds__(256) norm_kernel(float* __restrict__ out)
{
    int i = blockIdx.x * 256 + threadIdx.x;      // 0..63999 float4 index
    int b = i / (VOCAB / 4);                     // row (8000 float4 per row)
    float inv = 1.0f / g_rowsum[b];

    float4 v = ((const float4*)out)[i];
    v.x *= inv; v.y *= inv; v.z *= inv; v.w *= inv;
    ((float4*)out)[i] = v;

    __syncthreads();
    if (threadIdx.x == 0) {
        int d = atomicAdd(&g_norm_done, 1);
        if (d == NORM_GRID - 1) {
            for (int j = 0; j < BATCH; j++) g_rowsum[j] = 0.0f;
            __threadfence();
            g_norm_done = 0;
        }
    }
}

// ---------------------------------------------------------------------------
extern "C" void kernel_launch(void* const* d_in, const int* in_sizes, int n_in,
                              void* d_out, int out_size)
{
    const float* gru   = (const float*)d_in[0];
    const float* emb   = (const float*)d_in[1];
    const float* ctx   = (const float*)d_in[2];
    const int*   topic = (const int*)d_in[3];
    int T = in_sizes[3] / BATCH;

    const float* W_V = nullptr; const float* b_V = nullptr;
    const float* W_K = nullptr; const float* b_K = nullptr;
    for (int i = 4; i < n_in; ++i) {
        long sz = (long)in_sizes[i];
        if (sz == (long)VOCAB * XV && i + 1 < n_in) {
            W_V = (const float*)d_in[i];
            b_V = (const float*)d_in[i + 1];
        } else if (sz == (long)VOCAB * XK && i + 1 < n_in) {
            W_K = (const float*)d_in[i];
            b_K = (const float*)d_in[i + 1];
        }
    }

    float* out = (float*)d_out;

    static bool attr_set = false;
    if (!attr_set) {
        cudaFuncSetAttribute(ev_main_kernel,
                             cudaFuncAttributeMaxDynamicSharedMemorySize,
                             SMEM_BYTES);
        attr_set = true;
    }

    // 1) main e_v GEMM + row sums (R8 config: 2 CTAs/SM, static schedule)
    ev_main_kernel<<<CTAS, 256, SMEM_BYTES>>>(gru, emb, W_V, b_V, out);

    // 2) fused fixup: compute + dedup + apply + rowsum delta
    int nwarps  = BATCH * T;                      // 800
    int nblocks = (nwarps * 32 + 127) / 128;      // 200 CTAs
    ek_fixup_kernel<<<nblocks, 128>>>(gru, emb, ctx, topic, T, W_K, b_K, out);

    // 3) normalize + reset counters
    norm_kernel<<<NORM_GRID, 256>>>(out);
}